// round 3
// baseline (speedup 1.0000x reference)
#include <cuda_runtime.h>
#include <math.h>

#define BB     2
#define CEMB   256
#define KLAT   128
#define NLON   256
#define MM     129
#define MMP    132          // padded m for irfft A reads
#define LL     128
#define HID    512
#define NLAYER 4
#define PIX    (KLAT*NLON)  // 32768
#define BC     (BB*CEMB)    // 512
#define ROWS2  (BB*MM)      // 258
#define RC     (ROWS2*CEMB) // 66048
#define BCK    (BC*KLAT)    // 65536
#define NP     320          // padded spectral column count (5*64)

// ---------------- scratch (device globals; zero-initialized, no allocation) ----------------
__device__ float g_h [BB*CEMB*PIX];
__device__ float g_t [BB*HID*PIX];
__device__ float g_Fr[MM*BCK];
__device__ float g_Fi[MM*BCK];
__device__ float g_Dr[LL*RC];
__device__ float g_Di[LL*RC];
__device__ float g_Er[LL*RC];
__device__ float g_Ei[LL*RC];
__device__ float g_Yr[MMP*BCK];          // padding rows [129..131] stay zero
__device__ float g_Yi[MMP*BCK];
__device__ float g_Wtr[NLAYER*LL*CEMB*CEMB];
__device__ float g_Wti[NLAYER*LL*CEMB*CEMB];
__device__ float g_DFTf[NLON*NP];        // [n][c]  c=2m -> (2pi/256)cos, c=2m+1 -> -(2pi/256)sin
__device__ float g_DFTi[NP*NLON];        // [c][n]  c=2m -> s_m cos,      c=2m+1 -> -s_m sin

__device__ __forceinline__ float gelu_tanh(float x){
    float x3 = x*x*x;
    return 0.5f*x*(1.f + tanhf(0.7978845608028654f*fmaf(0.044715f, x3, x)));
}

// ---------------- DFT matrix init ----------------
__global__ void k_dftinit(){
    int c = blockIdx.x;      // 0..319
    int n = threadIdx.x;     // 0..255
    float fwdv = 0.f, invv = 0.f;
    if (c < 2*MM){
        int m = c >> 1;
        int ph = (m*n) & 255;
        double a = 6.283185307179586476925286766559 * (double)ph / 256.0;
        double base = (c & 1) ? -sin(a) : cos(a);
        fwdv = (float)(base * (6.283185307179586476925286766559/256.0));
        double s = (m==0 || m==MM-1) ? 1.0 : 2.0;
        invv = (float)(base * s);
    }
    g_DFTf[(size_t)n*NP + c]   = fwdv;
    g_DFTi[(size_t)c*NLON + n] = invv;
}

// ---------------- spec_w transpose: [layer][i][o][l][2] -> [layer][l][o][i] ----------------
__global__ void k_wtrans(const float* __restrict__ sw){
    int l  = blockIdx.x;
    int o  = blockIdx.y;
    int ly = blockIdx.z;
    int i  = threadIdx.x;
    size_t src = ((((size_t)ly*CEMB + i)*CEMB + o)*LL + l)*2;
    size_t dst = (((size_t)ly*LL + l)*CEMB + o)*CEMB + i;
    g_Wtr[dst] = sw[src];
    g_Wti[dst] = sw[src+1];
}

// ---------------- encoder ----------------
__global__ void k_encoder(const float* __restrict__ x, const float* __restrict__ wenc,
                          const float* __restrict__ benc, const float* __restrict__ pos){
    int b  = blockIdx.y;
    int p0 = blockIdx.x*256;
    int t  = threadIdx.x;
    __shared__ float ws[CEMB][8];
    #pragma unroll
    for (int j=0;j<8;j++) ws[t][j] = wenc[t*8+j];
    __syncthreads();
    float xv[8];
    #pragma unroll
    for (int c=0;c<8;c++) xv[c] = x[((size_t)b*8 + c)*PIX + p0 + t];
    for (int o=0;o<CEMB;o++){
        float acc = benc[o];
        #pragma unroll
        for (int c=0;c<8;c++) acc = fmaf(xv[c], ws[o][c], acc);
        g_h[((size_t)b*CEMB + o)*PIX + p0 + t] = acc + pos[(size_t)o*PIX + p0 + t];
    }
}

// ======================================================================
// GEMM kernels: 128x64 tile, BK=8, double-buffered, 8x4 per thread
// ======================================================================

// ---- fft forward: C[c][bck] = sum_n h[bck][n] * DFTf[n][c]
__global__ void __launch_bounds__(256) k_fft_fwd(){
    __shared__ float As[2][8][132];
    __shared__ float Bs[2][8][68];
    const int t=threadIdx.x, tx=t&15, ty=t>>4;
    const int bm0=blockIdx.x*128, bn0=blockIdx.y*64;
    const int ar=t>>1, aq=(t&1)*4;
    const int bk=t>>4, bq=(t&15)*4;
    float acc[8][4]={};
    {
        float4 a=*(const float4*)(g_h + (size_t)(bm0+ar)*NLON + aq);
        As[0][aq+0][ar]=a.x; As[0][aq+1][ar]=a.y; As[0][aq+2][ar]=a.z; As[0][aq+3][ar]=a.w;
        if (t<128) *(float4*)&Bs[0][bk][bq] = *(const float4*)(g_DFTf + (size_t)bk*NP + bn0+bq);
    }
    __syncthreads();
    int buf=0;
    for (int s=0;s<32;s++){
        float4 an, bn_;
        bool more = (s+1<32);
        if (more){
            int k0=(s+1)*8;
            an = *(const float4*)(g_h + (size_t)(bm0+ar)*NLON + k0+aq);
            if (t<128) bn_ = *(const float4*)(g_DFTf + (size_t)(k0+bk)*NP + bn0+bq);
        }
        #pragma unroll
        for (int kk=0;kk<8;kk++){
            float4 a0=*(const float4*)&As[buf][kk][ty*8];
            float4 a1=*(const float4*)&As[buf][kk][ty*8+4];
            float4 b =*(const float4*)&Bs[buf][kk][tx*4];
            float av[8]={a0.x,a0.y,a0.z,a0.w,a1.x,a1.y,a1.z,a1.w};
            float bv[4]={b.x,b.y,b.z,b.w};
            #pragma unroll
            for (int u=0;u<8;u++)
                #pragma unroll
                for (int v=0;v<4;v++) acc[u][v]=fmaf(av[u],bv[v],acc[u][v]);
        }
        if (more){
            int nb=buf^1;
            As[nb][aq+0][ar]=an.x; As[nb][aq+1][ar]=an.y; As[nb][aq+2][ar]=an.z; As[nb][aq+3][ar]=an.w;
            if (t<128) *(float4*)&Bs[nb][bk][bq]=bn_;
        }
        __syncthreads();
        buf^=1;
    }
    #pragma unroll
    for (int v=0;v<4;v++){
        int c = bn0+tx*4+v;
        if (c >= 2*MM) continue;
        float* dst = ((c&1)? g_Fi : g_Fr) + (size_t)(c>>1)*BCK + bm0 + ty*8;
        *(float4*)dst     = make_float4(acc[0][v],acc[1][v],acc[2][v],acc[3][v]);
        *(float4*)(dst+4) = make_float4(acc[4][v],acc[5][v],acc[6][v],acc[7][v]);
    }
}

// ---- Legendre fwd (per m): D[l][b][m][c] = sum_k F[m][bc][k] * wt[m][l][k]
__global__ void __launch_bounds__(256) k_legfwd(const float* __restrict__ wt){
    __shared__ float Asr[2][8][132], Asi[2][8][132];
    __shared__ float Bs[2][8][68];
    const int m=blockIdx.z;
    const int bm0=blockIdx.x*128, bn0=blockIdx.y*64;
    const int t=threadIdx.x, tx=t&15, ty=t>>4;
    const int ar=t>>1, aq=(t&1)*4;
    const int bl=(t>>1)&63, bq=(t&1)*4;
    const float* __restrict__ Ar = g_Fr + (size_t)m*BCK;
    const float* __restrict__ Ai = g_Fi + (size_t)m*BCK;
    const float* __restrict__ Bw = wt + (size_t)m*LL*KLAT;
    float accR[8][4]={}, accI[8][4]={};
    {
        float4 a=*(const float4*)(Ar + (size_t)(bm0+ar)*KLAT + aq);
        float4 i=*(const float4*)(Ai + (size_t)(bm0+ar)*KLAT + aq);
        Asr[0][aq+0][ar]=a.x; Asr[0][aq+1][ar]=a.y; Asr[0][aq+2][ar]=a.z; Asr[0][aq+3][ar]=a.w;
        Asi[0][aq+0][ar]=i.x; Asi[0][aq+1][ar]=i.y; Asi[0][aq+2][ar]=i.z; Asi[0][aq+3][ar]=i.w;
        if (t<128){
            float4 w=*(const float4*)(Bw + (size_t)(bn0+bl)*KLAT + bq);
            Bs[0][bq+0][bl]=w.x; Bs[0][bq+1][bl]=w.y; Bs[0][bq+2][bl]=w.z; Bs[0][bq+3][bl]=w.w;
        }
    }
    __syncthreads();
    int buf=0;
    for (int s=0;s<16;s++){
        float4 an, in_, wn;
        bool more=(s+1<16);
        if (more){
            int k0=(s+1)*8;
            an=*(const float4*)(Ar + (size_t)(bm0+ar)*KLAT + k0+aq);
            in_=*(const float4*)(Ai + (size_t)(bm0+ar)*KLAT + k0+aq);
            if (t<128) wn=*(const float4*)(Bw + (size_t)(bn0+bl)*KLAT + k0+bq);
        }
        #pragma unroll
        for (int kk=0;kk<8;kk++){
            float4 r0=*(const float4*)&Asr[buf][kk][ty*8];
            float4 r1=*(const float4*)&Asr[buf][kk][ty*8+4];
            float4 i0=*(const float4*)&Asi[buf][kk][ty*8];
            float4 i1=*(const float4*)&Asi[buf][kk][ty*8+4];
            float4 b =*(const float4*)&Bs[buf][kk][tx*4];
            float rv[8]={r0.x,r0.y,r0.z,r0.w,r1.x,r1.y,r1.z,r1.w};
            float iv[8]={i0.x,i0.y,i0.z,i0.w,i1.x,i1.y,i1.z,i1.w};
            float bv[4]={b.x,b.y,b.z,b.w};
            #pragma unroll
            for (int u=0;u<8;u++)
                #pragma unroll
                for (int v=0;v<4;v++){
                    accR[u][v]=fmaf(rv[u],bv[v],accR[u][v]);
                    accI[u][v]=fmaf(iv[u],bv[v],accI[u][v]);
                }
        }
        if (more){
            int nb=buf^1;
            Asr[nb][aq+0][ar]=an.x;  Asr[nb][aq+1][ar]=an.y;  Asr[nb][aq+2][ar]=an.z;  Asr[nb][aq+3][ar]=an.w;
            Asi[nb][aq+0][ar]=in_.x; Asi[nb][aq+1][ar]=in_.y; Asi[nb][aq+2][ar]=in_.z; Asi[nb][aq+3][ar]=in_.w;
            if (t<128){ Bs[nb][bq+0][bl]=wn.x; Bs[nb][bq+1][bl]=wn.y; Bs[nb][bq+2][bl]=wn.z; Bs[nb][bq+3][bl]=wn.w; }
        }
        __syncthreads();
        buf^=1;
    }
    const int b = bm0>>8;
    const int c0 = (bm0&255) + ty*8;
    #pragma unroll
    for (int v=0;v<4;v++){
        int l = bn0+tx*4+v;
        size_t o = (((size_t)l*BB + b)*MM + m)*CEMB + c0;
        *(float4*)(g_Dr+o)   = make_float4(accR[0][v],accR[1][v],accR[2][v],accR[3][v]);
        *(float4*)(g_Dr+o+4) = make_float4(accR[4][v],accR[5][v],accR[6][v],accR[7][v]);
        *(float4*)(g_Di+o)   = make_float4(accI[0][v],accI[1][v],accI[2][v],accI[3][v]);
        *(float4*)(g_Di+o+4) = make_float4(accI[4][v],accI[5][v],accI[6][v],accI[7][v]);
    }
}

// ---- dhconv (per l): complex E[row][o] = sum_i D[row][i] * W[o][i]
__global__ void __launch_bounds__(256) k_dhconv(int layer){
    __shared__ float Asr[2][8][132], Asi[2][8][132];
    __shared__ float Bsr[2][8][68],  Bsi[2][8][68];
    const int l=blockIdx.z;
    const int bm0=blockIdx.x*128, bn0=blockIdx.y*64;
    const int t=threadIdx.x, tx=t&15, ty=t>>4;
    const int ar=t>>1, aq=(t&1)*4;
    const int half=t>>7, t2=t&127;          // half 0 -> Br, 1 -> Bi
    const int bo=t2>>1, biq=(t2&1)*4;
    const float* __restrict__ Ar = g_Dr + (size_t)l*RC;
    const float* __restrict__ Ai = g_Di + (size_t)l*RC;
    const float* __restrict__ Br = g_Wtr + ((size_t)layer*LL + l)*CEMB*CEMB;
    const float* __restrict__ Bi = g_Wti + ((size_t)layer*LL + l)*CEMB*CEMB;
    const int arow = bm0+ar;
    const bool av = arow < ROWS2;
    float accR[8][4]={}, accI[8][4]={};
    {
        float4 a=make_float4(0,0,0,0), i=a;
        if (av){ a=*(const float4*)(Ar + (size_t)arow*CEMB + aq);
                 i=*(const float4*)(Ai + (size_t)arow*CEMB + aq); }
        Asr[0][aq+0][ar]=a.x; Asr[0][aq+1][ar]=a.y; Asr[0][aq+2][ar]=a.z; Asr[0][aq+3][ar]=a.w;
        Asi[0][aq+0][ar]=i.x; Asi[0][aq+1][ar]=i.y; Asi[0][aq+2][ar]=i.z; Asi[0][aq+3][ar]=i.w;
        const float* Bp = half ? Bi : Br;
        float4 w=*(const float4*)(Bp + (size_t)(bn0+bo)*CEMB + biq);
        float (*Bsp)[8][68] = half ? Bsi : Bsr;
        Bsp[0][biq+0][bo]=w.x; Bsp[0][biq+1][bo]=w.y; Bsp[0][biq+2][bo]=w.z; Bsp[0][biq+3][bo]=w.w;
    }
    __syncthreads();
    int buf=0;
    for (int s=0;s<32;s++){
        float4 an=make_float4(0,0,0,0), in_=an, wn;
        bool more=(s+1<32);
        if (more){
            int k0=(s+1)*8;
            if (av){ an=*(const float4*)(Ar + (size_t)arow*CEMB + k0+aq);
                     in_=*(const float4*)(Ai + (size_t)arow*CEMB + k0+aq); }
            const float* Bp = half ? Bi : Br;
            wn=*(const float4*)(Bp + (size_t)(bn0+bo)*CEMB + k0+biq);
        }
        #pragma unroll
        for (int kk=0;kk<8;kk++){
            float4 r0=*(const float4*)&Asr[buf][kk][ty*8];
            float4 r1=*(const float4*)&Asr[buf][kk][ty*8+4];
            float4 i0=*(const float4*)&Asi[buf][kk][ty*8];
            float4 i1=*(const float4*)&Asi[buf][kk][ty*8+4];
            float4 br=*(const float4*)&Bsr[buf][kk][tx*4];
            float4 bi=*(const float4*)&Bsi[buf][kk][tx*4];
            float rv[8]={r0.x,r0.y,r0.z,r0.w,r1.x,r1.y,r1.z,r1.w};
            float iv[8]={i0.x,i0.y,i0.z,i0.w,i1.x,i1.y,i1.z,i1.w};
            float brv[4]={br.x,br.y,br.z,br.w};
            float biv[4]={bi.x,bi.y,bi.z,bi.w};
            #pragma unroll
            for (int u=0;u<8;u++)
                #pragma unroll
                for (int v=0;v<4;v++){
                    accR[u][v]=fmaf(rv[u],brv[v],accR[u][v]);
                    accR[u][v]=fmaf(-iv[u],biv[v],accR[u][v]);
                    accI[u][v]=fmaf(rv[u],biv[v],accI[u][v]);
                    accI[u][v]=fmaf(iv[u],brv[v],accI[u][v]);
                }
        }
        if (more){
            int nb=buf^1;
            Asr[nb][aq+0][ar]=an.x;  Asr[nb][aq+1][ar]=an.y;  Asr[nb][aq+2][ar]=an.z;  Asr[nb][aq+3][ar]=an.w;
            Asi[nb][aq+0][ar]=in_.x; Asi[nb][aq+1][ar]=in_.y; Asi[nb][aq+2][ar]=in_.z; Asi[nb][aq+3][ar]=in_.w;
            float (*Bsp)[8][68] = half ? Bsi : Bsr;
            Bsp[nb][biq+0][bo]=wn.x; Bsp[nb][biq+1][bo]=wn.y; Bsp[nb][biq+2][bo]=wn.z; Bsp[nb][biq+3][bo]=wn.w;
        }
        __syncthreads();
        buf^=1;
    }
    #pragma unroll
    for (int u=0;u<8;u++){
        int row = bm0 + ty*8 + u;
        if (row >= ROWS2) continue;
        size_t o = (size_t)l*RC + (size_t)row*CEMB + bn0 + tx*4;
        *(float4*)(g_Er+o) = make_float4(accR[u][0],accR[u][1],accR[u][2],accR[u][3]);
        *(float4*)(g_Ei+o) = make_float4(accI[u][0],accI[u][1],accI[u][2],accI[u][3]);
    }
}

// ---- Legendre bwd (per m): Y[m][bc][k] = sum_l E[l][b][m][c] * iwt[m][l][k]
__global__ void __launch_bounds__(256) k_legbwd(const float* __restrict__ iwt){
    __shared__ float Asr[2][8][132], Asi[2][8][132];
    __shared__ float Bs[2][8][68];
    const int m=blockIdx.z;
    const int bm0=blockIdx.x*128, bn0=blockIdx.y*64;
    const int t=threadIdx.x, tx=t&15, ty=t>>4;
    const int la=t>>5, rq=(t&31)*4;
    const int bl=t>>4, bq=(t&15)*4;
    const int bT=bm0>>8, c0=bm0&255;
    const size_t abase = ((size_t)bT*MM + m)*CEMB + c0 + rq;
    const float* __restrict__ Bw = iwt + (size_t)m*LL*KLAT;
    float accR[8][4]={}, accI[8][4]={};
    {
        *(float4*)&Asr[0][la][rq] = *(const float4*)(g_Er + (size_t)la*RC + abase);
        *(float4*)&Asi[0][la][rq] = *(const float4*)(g_Ei + (size_t)la*RC + abase);
        if (t<128) *(float4*)&Bs[0][bl][bq] = *(const float4*)(Bw + (size_t)bl*KLAT + bn0+bq);
    }
    __syncthreads();
    int buf=0;
    for (int s=0;s<16;s++){
        float4 an, in_, wn;
        bool more=(s+1<16);
        if (more){
            int k0=(s+1)*8;
            an =*(const float4*)(g_Er + (size_t)(k0+la)*RC + abase);
            in_=*(const float4*)(g_Ei + (size_t)(k0+la)*RC + abase);
            if (t<128) wn=*(const float4*)(Bw + (size_t)(k0+bl)*KLAT + bn0+bq);
        }
        #pragma unroll
        for (int kk=0;kk<8;kk++){
            float4 r0=*(const float4*)&Asr[buf][kk][ty*8];
            float4 r1=*(const float4*)&Asr[buf][kk][ty*8+4];
            float4 i0=*(const float4*)&Asi[buf][kk][ty*8];
            float4 i1=*(const float4*)&Asi[buf][kk][ty*8+4];
            float4 b =*(const float4*)&Bs[buf][kk][tx*4];
            float rv[8]={r0.x,r0.y,r0.z,r0.w,r1.x,r1.y,r1.z,r1.w};
            float iv[8]={i0.x,i0.y,i0.z,i0.w,i1.x,i1.y,i1.z,i1.w};
            float bv[4]={b.x,b.y,b.z,b.w};
            #pragma unroll
            for (int u=0;u<8;u++)
                #pragma unroll
                for (int v=0;v<4;v++){
                    accR[u][v]=fmaf(rv[u],bv[v],accR[u][v]);
                    accI[u][v]=fmaf(iv[u],bv[v],accI[u][v]);
                }
        }
        if (more){
            int nb=buf^1;
            *(float4*)&Asr[nb][la][rq]=an;
            *(float4*)&Asi[nb][la][rq]=in_;
            if (t<128) *(float4*)&Bs[nb][bl][bq]=wn;
        }
        __syncthreads();
        buf^=1;
    }
    #pragma unroll
    for (int u=0;u<8;u++){
        int row = bm0 + ty*8 + u;
        size_t o = (size_t)m*BCK + (size_t)row*KLAT + bn0 + tx*4;
        *(float4*)(g_Yr+o) = make_float4(accR[u][0],accR[u][1],accR[u][2],accR[u][3]);
        *(float4*)(g_Yi+o) = make_float4(accI[u][0],accI[u][1],accI[u][2],accI[u][3]);
    }
}

// ---- fft inverse + gelu + residual: h[bck][n] = gelu(sum_c Y[c][bck]*DFTi[c][n]) + h
__global__ void __launch_bounds__(256) k_fft_inv(){
    __shared__ float As[2][8][132];
    __shared__ float Bs[2][8][68];
    const int t=threadIdx.x, tx=t&15, ty=t>>4;
    const int bm0=blockIdx.x*128, bn0=blockIdx.y*64;
    const int la=t>>5, rq=(t&31)*4;
    const int bk=t>>4, bq=(t&15)*4;
    float acc[8][4]={};
    {
        int km = la;
        const float* arr = (km&1) ? g_Yi : g_Yr;
        *(float4*)&As[0][la][rq] = *(const float4*)(arr + (size_t)(km>>1)*BCK + bm0+rq);
        if (t<128) *(float4*)&Bs[0][bk][bq] = *(const float4*)(g_DFTi + (size_t)bk*NLON + bn0+bq);
    }
    __syncthreads();
    int buf=0;
    const int NSTEP=33;          // covers K=258 (B rows >=258 are zero)
    for (int s=0;s<NSTEP;s++){
        float4 an, wn;
        bool more=(s+1<NSTEP);
        if (more){
            int k0=(s+1)*8;
            int km=k0+la;
            const float* arr = (km&1) ? g_Yi : g_Yr;
            an=*(const float4*)(arr + (size_t)(km>>1)*BCK + bm0+rq);
            if (t<128) wn=*(const float4*)(g_DFTi + (size_t)(k0+bk)*NLON + bn0+bq);
        }
        #pragma unroll
        for (int kk=0;kk<8;kk++){
            float4 a0=*(const float4*)&As[buf][kk][ty*8];
            float4 a1=*(const float4*)&As[buf][kk][ty*8+4];
            float4 b =*(const float4*)&Bs[buf][kk][tx*4];
            float av[8]={a0.x,a0.y,a0.z,a0.w,a1.x,a1.y,a1.z,a1.w};
            float bv[4]={b.x,b.y,b.z,b.w};
            #pragma unroll
            for (int u=0;u<8;u++)
                #pragma unroll
                for (int v=0;v<4;v++) acc[u][v]=fmaf(av[u],bv[v],acc[u][v]);
        }
        if (more){
            int nb=buf^1;
            *(float4*)&As[nb][la][rq]=an;
            if (t<128) *(float4*)&Bs[nb][bk][bq]=wn;
        }
        __syncthreads();
        buf^=1;
    }
    #pragma unroll
    for (int u=0;u<8;u++){
        int row = bm0 + ty*8 + u;
        size_t o = (size_t)row*NLON + bn0 + tx*4;
        float4 h = *(const float4*)(g_h+o);
        float4 r;
        r.x = gelu_tanh(acc[u][0]) + h.x;
        r.y = gelu_tanh(acc[u][1]) + h.y;
        r.z = gelu_tanh(acc[u][2]) + h.z;
        r.w = gelu_tanh(acc[u][3]) + h.w;
        *(float4*)(g_h+o) = r;
    }
}

// ---- MLP1: t = gelu(W1 h + b1)
__global__ void __launch_bounds__(256) k_mlp1(const float* __restrict__ W, const float* __restrict__ bias){
    __shared__ float As[2][8][132];
    __shared__ float Bs[2][8][68];
    const int bz=blockIdx.z;
    const int bm0=blockIdx.y*128, bn0=blockIdx.x*64;
    const int t=threadIdx.x, tx=t&15, ty=t>>4;
    const int ar=t>>1, aq=(t&1)*4;
    const int bk=t>>4, bq=(t&15)*4;
    const float* __restrict__ Bp = g_h + (size_t)bz*CEMB*PIX;
    float* __restrict__ Cp = g_t + (size_t)bz*HID*PIX;
    float acc[8][4]={};
    {
        float4 a=*(const float4*)(W + (size_t)(bm0+ar)*CEMB + aq);
        As[0][aq+0][ar]=a.x; As[0][aq+1][ar]=a.y; As[0][aq+2][ar]=a.z; As[0][aq+3][ar]=a.w;
        if (t<128) *(float4*)&Bs[0][bk][bq] = *(const float4*)(Bp + (size_t)bk*PIX + bn0+bq);
    }
    __syncthreads();
    int buf=0;
    for (int s=0;s<32;s++){
        float4 an, wn;
        bool more=(s+1<32);
        if (more){
            int k0=(s+1)*8;
            an=*(const float4*)(W + (size_t)(bm0+ar)*CEMB + k0+aq);
            if (t<128) wn=*(const float4*)(Bp + (size_t)(k0+bk)*PIX + bn0+bq);
        }
        #pragma unroll
        for (int kk=0;kk<8;kk++){
            float4 a0=*(const float4*)&As[buf][kk][ty*8];
            float4 a1=*(const float4*)&As[buf][kk][ty*8+4];
            float4 b =*(const float4*)&Bs[buf][kk][tx*4];
            float av[8]={a0.x,a0.y,a0.z,a0.w,a1.x,a1.y,a1.z,a1.w};
            float bv[4]={b.x,b.y,b.z,b.w};
            #pragma unroll
            for (int u=0;u<8;u++)
                #pragma unroll
                for (int v=0;v<4;v++) acc[u][v]=fmaf(av[u],bv[v],acc[u][v]);
        }
        if (more){
            int nb=buf^1;
            As[nb][aq+0][ar]=an.x; As[nb][aq+1][ar]=an.y; As[nb][aq+2][ar]=an.z; As[nb][aq+3][ar]=an.w;
            if (t<128) *(float4*)&Bs[nb][bk][bq]=wn;
        }
        __syncthreads();
        buf^=1;
    }
    #pragma unroll
    for (int u=0;u<8;u++){
        int row = bm0 + ty*8 + u;
        float bv = bias[row];
        size_t o = (size_t)row*PIX + bn0 + tx*4;
        float4 r;
        r.x = gelu_tanh(acc[u][0]+bv);
        r.y = gelu_tanh(acc[u][1]+bv);
        r.z = gelu_tanh(acc[u][2]+bv);
        r.w = gelu_tanh(acc[u][3]+bv);
        *(float4*)(Cp+o) = r;
    }
}

// ---- MLP2: h = W2 t + b2 + h
__global__ void __launch_bounds__(256) k_mlp2(const float* __restrict__ W, const float* __restrict__ bias){
    __shared__ float As[2][8][132];
    __shared__ float Bs[2][8][68];
    const int bz=blockIdx.z;
    const int bm0=blockIdx.y*128, bn0=blockIdx.x*64;
    const int t=threadIdx.x, tx=t&15, ty=t>>4;
    const int ar=t>>1, aq=(t&1)*4;
    const int bk=t>>4, bq=(t&15)*4;
    const float* __restrict__ Bp = g_t + (size_t)bz*HID*PIX;
    float* __restrict__ Cp = g_h + (size_t)bz*CEMB*PIX;
    float acc[8][4]={};
    {
        float4 a=*(const float4*)(W + (size_t)(bm0+ar)*HID + aq);
        As[0][aq+0][ar]=a.x; As[0][aq+1][ar]=a.y; As[0][aq+2][ar]=a.z; As[0][aq+3][ar]=a.w;
        if (t<128) *(float4*)&Bs[0][bk][bq] = *(const float4*)(Bp + (size_t)bk*PIX + bn0+bq);
    }
    __syncthreads();
    int buf=0;
    for (int s=0;s<64;s++){
        float4 an, wn;
        bool more=(s+1<64);
        if (more){
            int k0=(s+1)*8;
            an=*(const float4*)(W + (size_t)(bm0+ar)*HID + k0+aq);
            if (t<128) wn=*(const float4*)(Bp + (size_t)(k0+bk)*PIX + bn0+bq);
        }
        #pragma unroll
        for (int kk=0;kk<8;kk++){
            float4 a0=*(const float4*)&As[buf][kk][ty*8];
            float4 a1=*(const float4*)&As[buf][kk][ty*8+4];
            float4 b =*(const float4*)&Bs[buf][kk][tx*4];
            float av[8]={a0.x,a0.y,a0.z,a0.w,a1.x,a1.y,a1.z,a1.w};
            float bv[4]={b.x,b.y,b.z,b.w};
            #pragma unroll
            for (int u=0;u<8;u++)
                #pragma unroll
                for (int v=0;v<4;v++) acc[u][v]=fmaf(av[u],bv[v],acc[u][v]);
        }
        if (more){
            int nb=buf^1;
            As[nb][aq+0][ar]=an.x; As[nb][aq+1][ar]=an.y; As[nb][aq+2][ar]=an.z; As[nb][aq+3][ar]=an.w;
            if (t<128) *(float4*)&Bs[nb][bk][bq]=wn;
        }
        __syncthreads();
        buf^=1;
    }
    #pragma unroll
    for (int u=0;u<8;u++){
        int row = bm0 + ty*8 + u;
        float bv = bias[row];
        size_t o = (size_t)row*PIX + bn0 + tx*4;
        float4 h = *(const float4*)(Cp+o);
        float4 r;
        r.x = acc[u][0]+bv+h.x;
        r.y = acc[u][1]+bv+h.y;
        r.z = acc[u][2]+bv+h.z;
        r.w = acc[u][3]+bv+h.w;
        *(float4*)(Cp+o) = r;
    }
}

// ---------------- decoder ----------------
__global__ void k_decoder(const float* __restrict__ wdec, const float* __restrict__ bdec,
                          float* __restrict__ out){
    int b  = blockIdx.y;
    int p0 = blockIdx.x*256;
    int t  = threadIdx.x;
    __shared__ float ws[8][256];
    #pragma unroll
    for (int j=0;j<8;j++) ws[j][t] = wdec[j*CEMB + t];
    __syncthreads();
    float acc[8];
    #pragma unroll
    for (int o=0;o<8;o++) acc[o] = bdec[o];
    for (int c=0;c<CEMB;c++){
        float v = g_h[((size_t)b*CEMB + c)*PIX + p0 + t];
        #pragma unroll
        for (int o=0;o<8;o++) acc[o] = fmaf(v, ws[o][c], acc[o]);
    }
    #pragma unroll
    for (int o=0;o<8;o++)
        out[((size_t)b*8 + o)*PIX + p0 + t] = acc[o];
}

// ---------------- launch ----------------
extern "C" void kernel_launch(void* const* d_in, const int* in_sizes, int n_in,
                              void* d_out, int out_size){
    const float* x      = (const float*)d_in[0];
    const float* w_enc  = (const float*)d_in[1];
    const float* b_enc  = (const float*)d_in[2];
    const float* pos    = (const float*)d_in[3];
    const float* spec_w = (const float*)d_in[4];
    const float* w1     = (const float*)d_in[5];
    const float* b1     = (const float*)d_in[6];
    const float* w2     = (const float*)d_in[7];
    const float* b2     = (const float*)d_in[8];
    const float* w_dec  = (const float*)d_in[9];
    const float* b_dec  = (const float*)d_in[10];
    const float* sht_wt = (const float*)d_in[11];
    const float* isht_wt= (const float*)d_in[12];
    float* out = (float*)d_out;

    k_dftinit<<<NP,256>>>();
    k_wtrans<<<dim3(LL, CEMB, NLAYER), 256>>>(spec_w);
    k_encoder<<<dim3(PIX/256, BB), 256>>>(x, w_enc, b_enc, pos);

    for (int layer=0; layer<NLAYER; layer++){
        k_fft_fwd<<<dim3(BCK/128, NP/64), 256>>>();
        k_legfwd <<<dim3(BC/128, LL/64, MM), 256>>>(sht_wt);
        k_dhconv <<<dim3(3, CEMB/64, LL), 256>>>(layer);
        k_legbwd <<<dim3(BC/128, KLAT/64, MM), 256>>>(isht_wt);
        k_fft_inv<<<dim3(BCK/128, NLON/64), 256>>>();
        k_mlp1   <<<dim3(PIX/64, HID/128, BB), 256>>>(w1 + (size_t)layer*HID*CEMB,  b1 + layer*HID);
        k_mlp2   <<<dim3(PIX/64, CEMB/128, BB), 256>>>(w2 + (size_t)layer*CEMB*HID, b2 + layer*CEMB);
    }

    k_decoder<<<dim3(PIX/256, BB), 256>>>(w_dec, b_dec, out);
}

// round 4
// speedup vs baseline: 1.0810x; 1.0810x over previous
#include <cuda_runtime.h>
#include <math.h>

#define BB     2
#define CEMB   256
#define KLAT   128
#define NLON   256
#define MM     129
#define MMP    132
#define LL     128
#define HID    512
#define NLAYER 4
#define PIX    (KLAT*NLON)
#define BC     (BB*CEMB)
#define ROWS2  (BB*MM)
#define RC     (ROWS2*CEMB)
#define BCK    (BC*KLAT)
#define NP     320

typedef unsigned long long ull;

// ---------------- scratch ----------------
__device__ float g_h [BB*CEMB*PIX];
__device__ float g_t [BB*HID*PIX];
__device__ float g_Fr[MM*BCK];
__device__ float g_Fi[MM*BCK];
__device__ float g_Dr[LL*RC];
__device__ float g_Di[LL*RC];
__device__ float g_Er[LL*RC];
__device__ float g_Ei[LL*RC];
__device__ float g_Yr[MMP*BCK];
__device__ float g_Yi[MMP*BCK];
__device__ float g_Wtr[NLAYER*LL*CEMB*CEMB];
__device__ float g_Wti[NLAYER*LL*CEMB*CEMB];
__device__ float g_DFTf[NLON*NP];
__device__ float g_DFTi[NP*NLON];

__device__ __forceinline__ float gelu_tanh(float x){
    float x3 = x*x*x;
    return 0.5f*x*(1.f + tanhf(0.7978845608028654f*fmaf(0.044715f, x3, x)));
}

// ---- packed f32x2 helpers ----
__device__ __forceinline__ ull bcast2(float b){
    ull r; asm("mov.b64 %0, {%1, %1};" : "=l"(r) : "f"(b)); return r;
}
__device__ __forceinline__ void ffma2(ull &d, ull a, ull b){
    asm("fma.rn.f32x2 %0, %1, %2, %3;" : "=l"(d) : "l"(a), "l"(b), "l"(d));
}
union U4 { float4 f; ull u[2]; };
__device__ __forceinline__ float2 u2f(ull v){
    float2 r; asm("mov.b64 {%0, %1}, %2;" : "=f"(r.x), "=f"(r.y) : "l"(v)); return r;
}

// ---------------- DFT matrix init ----------------
__global__ void k_dftinit(){
    int c = blockIdx.x;
    int n = threadIdx.x;
    float fwdv = 0.f, invv = 0.f;
    if (c < 2*MM){
        int m = c >> 1;
        int ph = (m*n) & 255;
        double a = 6.283185307179586476925286766559 * (double)ph / 256.0;
        double base = (c & 1) ? -sin(a) : cos(a);
        fwdv = (float)(base * (6.283185307179586476925286766559/256.0));
        double s = (m==0 || m==MM-1) ? 1.0 : 2.0;
        invv = (float)(base * s);
    }
    g_DFTf[(size_t)n*NP + c]   = fwdv;
    g_DFTi[(size_t)c*NLON + n] = invv;
}

// ---------------- spec_w transpose ----------------
__global__ void k_wtrans(const float* __restrict__ sw){
    int l  = blockIdx.x;
    int o  = blockIdx.y;
    int ly = blockIdx.z;
    int i  = threadIdx.x;
    size_t src = ((((size_t)ly*CEMB + i)*CEMB + o)*LL + l)*2;
    size_t dst = (((size_t)ly*LL + l)*CEMB + o)*CEMB + i;
    g_Wtr[dst] = sw[src];
    g_Wti[dst] = sw[src+1];
}

// ---------------- encoder ----------------
__global__ void k_encoder(const float* __restrict__ x, const float* __restrict__ wenc,
                          const float* __restrict__ benc, const float* __restrict__ pos){
    int b  = blockIdx.y;
    int p0 = blockIdx.x*256;
    int t  = threadIdx.x;
    __shared__ float ws[CEMB][8];
    #pragma unroll
    for (int j=0;j<8;j++) ws[t][j] = wenc[t*8+j];
    __syncthreads();
    float xv[8];
    #pragma unroll
    for (int c=0;c<8;c++) xv[c] = x[((size_t)b*8 + c)*PIX + p0 + t];
    for (int o=0;o<CEMB;o++){
        float acc = benc[o];
        #pragma unroll
        for (int c=0;c<8;c++) acc = fmaf(xv[c], ws[o][c], acc);
        g_h[((size_t)b*CEMB + o)*PIX + p0 + t] = acc + pos[(size_t)o*PIX + p0 + t];
    }
}

// ======================================================================
// GEMM kernels: 128x64 tile, BK=8, double-buffered, FFMA2 inner loops
// ======================================================================

// ---- fft forward: C[c][bck] = sum_n h[bck][n] * DFTf[n][c]
__global__ void __launch_bounds__(256) k_fft_fwd(){
    __shared__ float As[2][8][132];
    __shared__ float Bs[2][8][68];
    const int t=threadIdx.x, tx=t&15, ty=t>>4;
    const int bm0=blockIdx.x*128, bn0=blockIdx.y*64;
    const int ar=t>>1, aq=(t&1)*4;
    const int bk=t>>4, bq=(t&15)*4;
    ull acc2[4][4]={};
    {
        float4 a=*(const float4*)(g_h + (size_t)(bm0+ar)*NLON + aq);
        As[0][aq+0][ar]=a.x; As[0][aq+1][ar]=a.y; As[0][aq+2][ar]=a.z; As[0][aq+3][ar]=a.w;
        if (t<128) *(float4*)&Bs[0][bk][bq] = *(const float4*)(g_DFTf + (size_t)bk*NP + bn0+bq);
    }
    __syncthreads();
    int buf=0;
    for (int s=0;s<32;s++){
        float4 an, bn_;
        bool more = (s+1<32);
        if (more){
            int k0=(s+1)*8;
            an = *(const float4*)(g_h + (size_t)(bm0+ar)*NLON + k0+aq);
            if (t<128) bn_ = *(const float4*)(g_DFTf + (size_t)(k0+bk)*NP + bn0+bq);
        }
        #pragma unroll
        for (int kk=0;kk<8;kk++){
            U4 A0, A1, B;
            A0.f=*(const float4*)&As[buf][kk][ty*8];
            A1.f=*(const float4*)&As[buf][kk][ty*8+4];
            B.f =*(const float4*)&Bs[buf][kk][tx*4];
            ull av[4]={A0.u[0],A0.u[1],A1.u[0],A1.u[1]};
            float bvf[4]={B.f.x,B.f.y,B.f.z,B.f.w};
            #pragma unroll
            for (int v=0;v<4;v++){
                ull bb = bcast2(bvf[v]);
                #pragma unroll
                for (int u=0;u<4;u++) ffma2(acc2[u][v], av[u], bb);
            }
        }
        if (more){
            int nb=buf^1;
            As[nb][aq+0][ar]=an.x; As[nb][aq+1][ar]=an.y; As[nb][aq+2][ar]=an.z; As[nb][aq+3][ar]=an.w;
            if (t<128) *(float4*)&Bs[nb][bk][bq]=bn_;
        }
        __syncthreads();
        buf^=1;
    }
    #pragma unroll
    for (int v=0;v<4;v++){
        int c = bn0+tx*4+v;
        if (c >= 2*MM) continue;
        float2 f0=u2f(acc2[0][v]), f1=u2f(acc2[1][v]), f2=u2f(acc2[2][v]), f3=u2f(acc2[3][v]);
        float* dst = ((c&1)? g_Fi : g_Fr) + (size_t)(c>>1)*BCK + bm0 + ty*8;
        *(float4*)dst     = make_float4(f0.x,f0.y,f1.x,f1.y);
        *(float4*)(dst+4) = make_float4(f2.x,f2.y,f3.x,f3.y);
    }
}

// ---- Legendre fwd (per m)
__global__ void __launch_bounds__(256) k_legfwd(const float* __restrict__ wt){
    __shared__ float Asr[2][8][132], Asi[2][8][132];
    __shared__ float Bs[2][8][68];
    const int m=blockIdx.z;
    const int bm0=blockIdx.x*128, bn0=blockIdx.y*64;
    const int t=threadIdx.x, tx=t&15, ty=t>>4;
    const int ar=t>>1, aq=(t&1)*4;
    const int bl=(t>>1)&63, bq=(t&1)*4;
    const float* __restrict__ Ar = g_Fr + (size_t)m*BCK;
    const float* __restrict__ Ai = g_Fi + (size_t)m*BCK;
    const float* __restrict__ Bw = wt + (size_t)m*LL*KLAT;
    ull accR2[4][4]={}, accI2[4][4]={};
    {
        float4 a=*(const float4*)(Ar + (size_t)(bm0+ar)*KLAT + aq);
        float4 i=*(const float4*)(Ai + (size_t)(bm0+ar)*KLAT + aq);
        Asr[0][aq+0][ar]=a.x; Asr[0][aq+1][ar]=a.y; Asr[0][aq+2][ar]=a.z; Asr[0][aq+3][ar]=a.w;
        Asi[0][aq+0][ar]=i.x; Asi[0][aq+1][ar]=i.y; Asi[0][aq+2][ar]=i.z; Asi[0][aq+3][ar]=i.w;
        if (t<128){
            float4 w=*(const float4*)(Bw + (size_t)(bn0+bl)*KLAT + bq);
            Bs[0][bq+0][bl]=w.x; Bs[0][bq+1][bl]=w.y; Bs[0][bq+2][bl]=w.z; Bs[0][bq+3][bl]=w.w;
        }
    }
    __syncthreads();
    int buf=0;
    for (int s=0;s<16;s++){
        float4 an, in_, wn;
        bool more=(s+1<16);
        if (more){
            int k0=(s+1)*8;
            an=*(const float4*)(Ar + (size_t)(bm0+ar)*KLAT + k0+aq);
            in_=*(const float4*)(Ai + (size_t)(bm0+ar)*KLAT + k0+aq);
            if (t<128) wn=*(const float4*)(Bw + (size_t)(bn0+bl)*KLAT + k0+bq);
        }
        #pragma unroll
        for (int kk=0;kk<8;kk++){
            U4 R0,R1,I0,I1,B;
            R0.f=*(const float4*)&Asr[buf][kk][ty*8];
            R1.f=*(const float4*)&Asr[buf][kk][ty*8+4];
            I0.f=*(const float4*)&Asi[buf][kk][ty*8];
            I1.f=*(const float4*)&Asi[buf][kk][ty*8+4];
            B.f =*(const float4*)&Bs[buf][kk][tx*4];
            ull rv[4]={R0.u[0],R0.u[1],R1.u[0],R1.u[1]};
            ull iv[4]={I0.u[0],I0.u[1],I1.u[0],I1.u[1]};
            float bvf[4]={B.f.x,B.f.y,B.f.z,B.f.w};
            #pragma unroll
            for (int v=0;v<4;v++){
                ull bb = bcast2(bvf[v]);
                #pragma unroll
                for (int u=0;u<4;u++){
                    ffma2(accR2[u][v], rv[u], bb);
                    ffma2(accI2[u][v], iv[u], bb);
                }
            }
        }
        if (more){
            int nb=buf^1;
            Asr[nb][aq+0][ar]=an.x;  Asr[nb][aq+1][ar]=an.y;  Asr[nb][aq+2][ar]=an.z;  Asr[nb][aq+3][ar]=an.w;
            Asi[nb][aq+0][ar]=in_.x; Asi[nb][aq+1][ar]=in_.y; Asi[nb][aq+2][ar]=in_.z; Asi[nb][aq+3][ar]=in_.w;
            if (t<128){ Bs[nb][bq+0][bl]=wn.x; Bs[nb][bq+1][bl]=wn.y; Bs[nb][bq+2][bl]=wn.z; Bs[nb][bq+3][bl]=wn.w; }
        }
        __syncthreads();
        buf^=1;
    }
    const int b = bm0>>8;
    const int c0 = (bm0&255) + ty*8;
    #pragma unroll
    for (int v=0;v<4;v++){
        int l = bn0+tx*4+v;
        size_t o = (((size_t)l*BB + b)*MM + m)*CEMB + c0;
        float2 r0=u2f(accR2[0][v]), r1=u2f(accR2[1][v]), r2=u2f(accR2[2][v]), r3=u2f(accR2[3][v]);
        float2 i0=u2f(accI2[0][v]), i1=u2f(accI2[1][v]), i2=u2f(accI2[2][v]), i3=u2f(accI2[3][v]);
        *(float4*)(g_Dr+o)   = make_float4(r0.x,r0.y,r1.x,r1.y);
        *(float4*)(g_Dr+o+4) = make_float4(r2.x,r2.y,r3.x,r3.y);
        *(float4*)(g_Di+o)   = make_float4(i0.x,i0.y,i1.x,i1.y);
        *(float4*)(g_Di+o+4) = make_float4(i2.x,i2.y,i3.x,i3.y);
    }
}

// ---- dhconv (per l): complex
__global__ void __launch_bounds__(256) k_dhconv(int layer){
    __shared__ float Asr[2][8][132], Asi[2][8][132];
    __shared__ float Bsr[2][8][68],  Bsi[2][8][68];
    const int l=blockIdx.z;
    const int bm0=blockIdx.x*128, bn0=blockIdx.y*64;
    const int t=threadIdx.x, tx=t&15, ty=t>>4;
    const int ar=t>>1, aq=(t&1)*4;
    const int half=t>>7, t2=t&127;
    const int bo=t2>>1, biq=(t2&1)*4;
    const float* __restrict__ Ar = g_Dr + (size_t)l*RC;
    const float* __restrict__ Ai = g_Di + (size_t)l*RC;
    const float* __restrict__ Br = g_Wtr + ((size_t)layer*LL + l)*CEMB*CEMB;
    const float* __restrict__ Bi = g_Wti + ((size_t)layer*LL + l)*CEMB*CEMB;
    const int arow = bm0+ar;
    const bool av = arow < ROWS2;
    ull accR2[4][4]={}, accI2[4][4]={};
    {
        float4 a=make_float4(0,0,0,0), i=a;
        if (av){ a=*(const float4*)(Ar + (size_t)arow*CEMB + aq);
                 i=*(const float4*)(Ai + (size_t)arow*CEMB + aq); }
        Asr[0][aq+0][ar]=a.x; Asr[0][aq+1][ar]=a.y; Asr[0][aq+2][ar]=a.z; Asr[0][aq+3][ar]=a.w;
        Asi[0][aq+0][ar]=i.x; Asi[0][aq+1][ar]=i.y; Asi[0][aq+2][ar]=i.z; Asi[0][aq+3][ar]=i.w;
        const float* Bp = half ? Bi : Br;
        float4 w=*(const float4*)(Bp + (size_t)(bn0+bo)*CEMB + biq);
        float (*Bsp)[8][68] = half ? Bsi : Bsr;
        Bsp[0][biq+0][bo]=w.x; Bsp[0][biq+1][bo]=w.y; Bsp[0][biq+2][bo]=w.z; Bsp[0][biq+3][bo]=w.w;
    }
    __syncthreads();
    int buf=0;
    for (int s=0;s<32;s++){
        float4 an=make_float4(0,0,0,0), in_=an, wn;
        bool more=(s+1<32);
        if (more){
            int k0=(s+1)*8;
            if (av){ an=*(const float4*)(Ar + (size_t)arow*CEMB + k0+aq);
                     in_=*(const float4*)(Ai + (size_t)arow*CEMB + k0+aq); }
            const float* Bp = half ? Bi : Br;
            wn=*(const float4*)(Bp + (size_t)(bn0+bo)*CEMB + k0+biq);
        }
        #pragma unroll
        for (int kk=0;kk<8;kk++){
            U4 R0,R1,I0,I1,BR,BI;
            R0.f=*(const float4*)&Asr[buf][kk][ty*8];
            R1.f=*(const float4*)&Asr[buf][kk][ty*8+4];
            I0.f=*(const float4*)&Asi[buf][kk][ty*8];
            I1.f=*(const float4*)&Asi[buf][kk][ty*8+4];
            BR.f=*(const float4*)&Bsr[buf][kk][tx*4];
            BI.f=*(const float4*)&Bsi[buf][kk][tx*4];
            ull rv[4]={R0.u[0],R0.u[1],R1.u[0],R1.u[1]};
            ull iv[4]={I0.u[0],I0.u[1],I1.u[0],I1.u[1]};
            float brf[4]={BR.f.x,BR.f.y,BR.f.z,BR.f.w};
            float bif[4]={BI.f.x,BI.f.y,BI.f.z,BI.f.w};
            #pragma unroll
            for (int v=0;v<4;v++){
                ull bbr = bcast2(brf[v]);
                ull bbi = bcast2(bif[v]);
                ull nbi = bcast2(-bif[v]);
                #pragma unroll
                for (int u=0;u<4;u++){
                    ffma2(accR2[u][v], rv[u], bbr);
                    ffma2(accR2[u][v], iv[u], nbi);
                    ffma2(accI2[u][v], rv[u], bbi);
                    ffma2(accI2[u][v], iv[u], bbr);
                }
            }
        }
        if (more){
            int nb=buf^1;
            Asr[nb][aq+0][ar]=an.x;  Asr[nb][aq+1][ar]=an.y;  Asr[nb][aq+2][ar]=an.z;  Asr[nb][aq+3][ar]=an.w;
            Asi[nb][aq+0][ar]=in_.x; Asi[nb][aq+1][ar]=in_.y; Asi[nb][aq+2][ar]=in_.z; Asi[nb][aq+3][ar]=in_.w;
            float (*Bsp)[8][68] = half ? Bsi : Bsr;
            Bsp[nb][biq+0][bo]=wn.x; Bsp[nb][biq+1][bo]=wn.y; Bsp[nb][biq+2][bo]=wn.z; Bsp[nb][biq+3][bo]=wn.w;
        }
        __syncthreads();
        buf^=1;
    }
    #pragma unroll
    for (int u2=0;u2<4;u2++){
        #pragma unroll
        for (int p=0;p<2;p++){
            int row = bm0 + ty*8 + u2*2 + p;
            if (row >= ROWS2) continue;
            size_t o = (size_t)l*RC + (size_t)row*CEMB + bn0 + tx*4;
            float2 r0=u2f(accR2[u2][0]), r1=u2f(accR2[u2][1]), r2=u2f(accR2[u2][2]), r3=u2f(accR2[u2][3]);
            float2 i0=u2f(accI2[u2][0]), i1=u2f(accI2[u2][1]), i2=u2f(accI2[u2][2]), i3=u2f(accI2[u2][3]);
            if (p==0){
                *(float4*)(g_Er+o) = make_float4(r0.x,r1.x,r2.x,r3.x);
                *(float4*)(g_Ei+o) = make_float4(i0.x,i1.x,i2.x,i3.x);
            } else {
                *(float4*)(g_Er+o) = make_float4(r0.y,r1.y,r2.y,r3.y);
                *(float4*)(g_Ei+o) = make_float4(i0.y,i1.y,i2.y,i3.y);
            }
        }
    }
}

// ---- Legendre bwd (per m)
__global__ void __launch_bounds__(256) k_legbwd(const float* __restrict__ iwt){
    __shared__ float Asr[2][8][132], Asi[2][8][132];
    __shared__ float Bs[2][8][68];
    const int m=blockIdx.z;
    const int bm0=blockIdx.x*128, bn0=blockIdx.y*64;
    const int t=threadIdx.x, tx=t&15, ty=t>>4;
    const int la=t>>5, rq=(t&31)*4;
    const int bl=t>>4, bq=(t&15)*4;
    const int bT=bm0>>8, c0=bm0&255;
    const size_t abase = ((size_t)bT*MM + m)*CEMB + c0 + rq;
    const float* __restrict__ Bw = iwt + (size_t)m*LL*KLAT;
    ull accR2[4][4]={}, accI2[4][4]={};
    {
        *(float4*)&Asr[0][la][rq] = *(const float4*)(g_Er + (size_t)la*RC + abase);
        *(float4*)&Asi[0][la][rq] = *(const float4*)(g_Ei + (size_t)la*RC + abase);
        if (t<128) *(float4*)&Bs[0][bl][bq] = *(const float4*)(Bw + (size_t)bl*KLAT + bn0+bq);
    }
    __syncthreads();
    int buf=0;
    for (int s=0;s<16;s++){
        float4 an, in_, wn;
        bool more=(s+1<16);
        if (more){
            int k0=(s+1)*8;
            an =*(const float4*)(g_Er + (size_t)(k0+la)*RC + abase);
            in_=*(const float4*)(g_Ei + (size_t)(k0+la)*RC + abase);
            if (t<128) wn=*(const float4*)(Bw + (size_t)(k0+bl)*KLAT + bn0+bq);
        }
        #pragma unroll
        for (int kk=0;kk<8;kk++){
            U4 R0,R1,I0,I1,B;
            R0.f=*(const float4*)&Asr[buf][kk][ty*8];
            R1.f=*(const float4*)&Asr[buf][kk][ty*8+4];
            I0.f=*(const float4*)&Asi[buf][kk][ty*8];
            I1.f=*(const float4*)&Asi[buf][kk][ty*8+4];
            B.f =*(const float4*)&Bs[buf][kk][tx*4];
            ull rv[4]={R0.u[0],R0.u[1],R1.u[0],R1.u[1]};
            ull iv[4]={I0.u[0],I0.u[1],I1.u[0],I1.u[1]};
            float bvf[4]={B.f.x,B.f.y,B.f.z,B.f.w};
            #pragma unroll
            for (int v=0;v<4;v++){
                ull bb = bcast2(bvf[v]);
                #pragma unroll
                for (int u=0;u<4;u++){
                    ffma2(accR2[u][v], rv[u], bb);
                    ffma2(accI2[u][v], iv[u], bb);
                }
            }
        }
        if (more){
            int nb=buf^1;
            *(float4*)&Asr[nb][la][rq]=an;
            *(float4*)&Asi[nb][la][rq]=in_;
            if (t<128) *(float4*)&Bs[nb][bl][bq]=wn;
        }
        __syncthreads();
        buf^=1;
    }
    #pragma unroll
    for (int u2=0;u2<4;u2++){
        float2 r0=u2f(accR2[u2][0]), r1=u2f(accR2[u2][1]), r2=u2f(accR2[u2][2]), r3=u2f(accR2[u2][3]);
        float2 i0=u2f(accI2[u2][0]), i1=u2f(accI2[u2][1]), i2=u2f(accI2[u2][2]), i3=u2f(accI2[u2][3]);
        int row0 = bm0 + ty*8 + u2*2;
        size_t o0 = (size_t)m*BCK + (size_t)row0*KLAT + bn0 + tx*4;
        *(float4*)(g_Yr+o0)      = make_float4(r0.x,r1.x,r2.x,r3.x);
        *(float4*)(g_Yi+o0)      = make_float4(i0.x,i1.x,i2.x,i3.x);
        *(float4*)(g_Yr+o0+KLAT) = make_float4(r0.y,r1.y,r2.y,r3.y);
        *(float4*)(g_Yi+o0+KLAT) = make_float4(i0.y,i1.y,i2.y,i3.y);
    }
}

// ---- fft inverse + gelu + residual
__global__ void __launch_bounds__(256) k_fft_inv(){
    __shared__ float As[2][8][132];
    __shared__ float Bs[2][8][68];
    const int t=threadIdx.x, tx=t&15, ty=t>>4;
    const int bm0=blockIdx.x*128, bn0=blockIdx.y*64;
    const int la=t>>5, rq=(t&31)*4;
    const int bk=t>>4, bq=(t&15)*4;
    ull acc2[4][4]={};
    {
        int km = la;
        const float* arr = (km&1) ? g_Yi : g_Yr;
        *(float4*)&As[0][la][rq] = *(const float4*)(arr + (size_t)(km>>1)*BCK + bm0+rq);
        if (t<128) *(float4*)&Bs[0][bk][bq] = *(const float4*)(g_DFTi + (size_t)bk*NLON + bn0+bq);
    }
    __syncthreads();
    int buf=0;
    const int NSTEP=33;
    for (int s=0;s<NSTEP;s++){
        float4 an, wn;
        bool more=(s+1<NSTEP);
        if (more){
            int k0=(s+1)*8;
            int km=k0+la;
            const float* arr = (km&1) ? g_Yi : g_Yr;
            an=*(const float4*)(arr + (size_t)(km>>1)*BCK + bm0+rq);
            if (t<128) wn=*(const float4*)(g_DFTi + (size_t)(k0+bk)*NLON + bn0+bq);
        }
        #pragma unroll
        for (int kk=0;kk<8;kk++){
            U4 A0,A1,B;
            A0.f=*(const float4*)&As[buf][kk][ty*8];
            A1.f=*(const float4*)&As[buf][kk][ty*8+4];
            B.f =*(const float4*)&Bs[buf][kk][tx*4];
            ull av[4]={A0.u[0],A0.u[1],A1.u[0],A1.u[1]};
            float bvf[4]={B.f.x,B.f.y,B.f.z,B.f.w};
            #pragma unroll
            for (int v=0;v<4;v++){
                ull bb = bcast2(bvf[v]);
                #pragma unroll
                for (int u=0;u<4;u++) ffma2(acc2[u][v], av[u], bb);
            }
        }
        if (more){
            int nb=buf^1;
            *(float4*)&As[nb][la][rq]=an;
            if (t<128) *(float4*)&Bs[nb][bk][bq]=wn;
        }
        __syncthreads();
        buf^=1;
    }
    #pragma unroll
    for (int u2=0;u2<4;u2++){
        float2 f0=u2f(acc2[u2][0]), f1=u2f(acc2[u2][1]), f2=u2f(acc2[u2][2]), f3=u2f(acc2[u2][3]);
        float rowv[2][4]={{f0.x,f1.x,f2.x,f3.x},{f0.y,f1.y,f2.y,f3.y}};
        #pragma unroll
        for (int p=0;p<2;p++){
            int row = bm0 + ty*8 + u2*2 + p;
            size_t o = (size_t)row*NLON + bn0 + tx*4;
            float4 h = *(const float4*)(g_h+o);
            float4 r;
            r.x = gelu_tanh(rowv[p][0]) + h.x;
            r.y = gelu_tanh(rowv[p][1]) + h.y;
            r.z = gelu_tanh(rowv[p][2]) + h.z;
            r.w = gelu_tanh(rowv[p][3]) + h.w;
            *(float4*)(g_h+o) = r;
        }
    }
}

// ---- MLP1
__global__ void __launch_bounds__(256) k_mlp1(const float* __restrict__ W, const float* __restrict__ bias){
    __shared__ float As[2][8][132];
    __shared__ float Bs[2][8][68];
    const int bz=blockIdx.z;
    const int bm0=blockIdx.y*128, bn0=blockIdx.x*64;
    const int t=threadIdx.x, tx=t&15, ty=t>>4;
    const int ar=t>>1, aq=(t&1)*4;
    const int bk=t>>4, bq=(t&15)*4;
    const float* __restrict__ Bp = g_h + (size_t)bz*CEMB*PIX;
    float* __restrict__ Cp = g_t + (size_t)bz*HID*PIX;
    ull acc2[4][4]={};
    {
        float4 a=*(const float4*)(W + (size_t)(bm0+ar)*CEMB + aq);
        As[0][aq+0][ar]=a.x; As[0][aq+1][ar]=a.y; As[0][aq+2][ar]=a.z; As[0][aq+3][ar]=a.w;
        if (t<128) *(float4*)&Bs[0][bk][bq] = *(const float4*)(Bp + (size_t)bk*PIX + bn0+bq);
    }
    __syncthreads();
    int buf=0;
    for (int s=0;s<32;s++){
        float4 an, wn;
        bool more=(s+1<32);
        if (more){
            int k0=(s+1)*8;
            an=*(const float4*)(W + (size_t)(bm0+ar)*CEMB + k0+aq);
            if (t<128) wn=*(const float4*)(Bp + (size_t)(k0+bk)*PIX + bn0+bq);
        }
        #pragma unroll
        for (int kk=0;kk<8;kk++){
            U4 A0,A1,B;
            A0.f=*(const float4*)&As[buf][kk][ty*8];
            A1.f=*(const float4*)&As[buf][kk][ty*8+4];
            B.f =*(const float4*)&Bs[buf][kk][tx*4];
            ull av[4]={A0.u[0],A0.u[1],A1.u[0],A1.u[1]};
            float bvf[4]={B.f.x,B.f.y,B.f.z,B.f.w};
            #pragma unroll
            for (int v=0;v<4;v++){
                ull bb = bcast2(bvf[v]);
                #pragma unroll
                for (int u=0;u<4;u++) ffma2(acc2[u][v], av[u], bb);
            }
        }
        if (more){
            int nb=buf^1;
            As[nb][aq+0][ar]=an.x; As[nb][aq+1][ar]=an.y; As[nb][aq+2][ar]=an.z; As[nb][aq+3][ar]=an.w;
            if (t<128) *(float4*)&Bs[nb][bk][bq]=wn;
        }
        __syncthreads();
        buf^=1;
    }
    #pragma unroll
    for (int u2=0;u2<4;u2++){
        float2 f0=u2f(acc2[u2][0]), f1=u2f(acc2[u2][1]), f2=u2f(acc2[u2][2]), f3=u2f(acc2[u2][3]);
        float rowv[2][4]={{f0.x,f1.x,f2.x,f3.x},{f0.y,f1.y,f2.y,f3.y}};
        #pragma unroll
        for (int p=0;p<2;p++){
            int row = bm0 + ty*8 + u2*2 + p;
            float bv = bias[row];
            size_t o = (size_t)row*PIX + bn0 + tx*4;
            float4 r;
            r.x = gelu_tanh(rowv[p][0]+bv);
            r.y = gelu_tanh(rowv[p][1]+bv);
            r.z = gelu_tanh(rowv[p][2]+bv);
            r.w = gelu_tanh(rowv[p][3]+bv);
            *(float4*)(Cp+o) = r;
        }
    }
}

// ---- MLP2
__global__ void __launch_bounds__(256) k_mlp2(const float* __restrict__ W, const float* __restrict__ bias){
    __shared__ float As[2][8][132];
    __shared__ float Bs[2][8][68];
    const int bz=blockIdx.z;
    const int bm0=blockIdx.y*128, bn0=blockIdx.x*64;
    const int t=threadIdx.x, tx=t&15, ty=t>>4;
    const int ar=t>>1, aq=(t&1)*4;
    const int bk=t>>4, bq=(t&15)*4;
    const float* __restrict__ Bp = g_t + (size_t)bz*HID*PIX;
    float* __restrict__ Cp = g_h + (size_t)bz*CEMB*PIX;
    ull acc2[4][4]={};
    {
        float4 a=*(const float4*)(W + (size_t)(bm0+ar)*HID + aq);
        As[0][aq+0][ar]=a.x; As[0][aq+1][ar]=a.y; As[0][aq+2][ar]=a.z; As[0][aq+3][ar]=a.w;
        if (t<128) *(float4*)&Bs[0][bk][bq] = *(const float4*)(Bp + (size_t)bk*PIX + bn0+bq);
    }
    __syncthreads();
    int buf=0;
    for (int s=0;s<64;s++){
        float4 an, wn;
        bool more=(s+1<64);
        if (more){
            int k0=(s+1)*8;
            an=*(const float4*)(W + (size_t)(bm0+ar)*HID + k0+aq);
            if (t<128) wn=*(const float4*)(Bp + (size_t)(k0+bk)*PIX + bn0+bq);
        }
        #pragma unroll
        for (int kk=0;kk<8;kk++){
            U4 A0,A1,B;
            A0.f=*(const float4*)&As[buf][kk][ty*8];
            A1.f=*(const float4*)&As[buf][kk][ty*8+4];
            B.f =*(const float4*)&Bs[buf][kk][tx*4];
            ull av[4]={A0.u[0],A0.u[1],A1.u[0],A1.u[1]};
            float bvf[4]={B.f.x,B.f.y,B.f.z,B.f.w};
            #pragma unroll
            for (int v=0;v<4;v++){
                ull bb = bcast2(bvf[v]);
                #pragma unroll
                for (int u=0;u<4;u++) ffma2(acc2[u][v], av[u], bb);
            }
        }
        if (more){
            int nb=buf^1;
            As[nb][aq+0][ar]=an.x; As[nb][aq+1][ar]=an.y; As[nb][aq+2][ar]=an.z; As[nb][aq+3][ar]=an.w;
            if (t<128) *(float4*)&Bs[nb][bk][bq]=wn;
        }
        __syncthreads();
        buf^=1;
    }
    #pragma unroll
    for (int u2=0;u2<4;u2++){
        float2 f0=u2f(acc2[u2][0]), f1=u2f(acc2[u2][1]), f2=u2f(acc2[u2][2]), f3=u2f(acc2[u2][3]);
        float rowv[2][4]={{f0.x,f1.x,f2.x,f3.x},{f0.y,f1.y,f2.y,f3.y}};
        #pragma unroll
        for (int p=0;p<2;p++){
            int row = bm0 + ty*8 + u2*2 + p;
            float bv = bias[row];
            size_t o = (size_t)row*PIX + bn0 + tx*4;
            float4 h = *(const float4*)(Cp+o);
            float4 r;
            r.x = rowv[p][0]+bv+h.x;
            r.y = rowv[p][1]+bv+h.y;
            r.z = rowv[p][2]+bv+h.z;
            r.w = rowv[p][3]+bv+h.w;
            *(float4*)(Cp+o) = r;
        }
    }
}

// ---------------- decoder ----------------
__global__ void k_decoder(const float* __restrict__ wdec, const float* __restrict__ bdec,
                          float* __restrict__ out){
    int b  = blockIdx.y;
    int p0 = blockIdx.x*256;
    int t  = threadIdx.x;
    __shared__ float ws[8][256];
    #pragma unroll
    for (int j=0;j<8;j++) ws[j][t] = wdec[j*CEMB + t];
    __syncthreads();
    float acc[8];
    #pragma unroll
    for (int o=0;o<8;o++) acc[o] = bdec[o];
    for (int c=0;c<CEMB;c++){
        float v = g_h[((size_t)b*CEMB + c)*PIX + p0 + t];
        #pragma unroll
        for (int o=0;o<8;o++) acc[o] = fmaf(v, ws[o][c], acc[o]);
    }
    #pragma unroll
    for (int o=0;o<8;o++)
        out[((size_t)b*8 + o)*PIX + p0 + t] = acc[o];
}

// ---------------- launch ----------------
extern "C" void kernel_launch(void* const* d_in, const int* in_sizes, int n_in,
                              void* d_out, int out_size){
    const float* x      = (const float*)d_in[0];
    const float* w_enc  = (const float*)d_in[1];
    const float* b_enc  = (const float*)d_in[2];
    const float* pos    = (const float*)d_in[3];
    const float* spec_w = (const float*)d_in[4];
    const float* w1     = (const float*)d_in[5];
    const float* b1     = (const float*)d_in[6];
    const float* w2     = (const float*)d_in[7];
    const float* b2     = (const float*)d_in[8];
    const float* w_dec  = (const float*)d_in[9];
    const float* b_dec  = (const float*)d_in[10];
    const float* sht_wt = (const float*)d_in[11];
    const float* isht_wt= (const float*)d_in[12];
    float* out = (float*)d_out;

    k_dftinit<<<NP,256>>>();
    k_wtrans<<<dim3(LL, CEMB, NLAYER), 256>>>(spec_w);
    k_encoder<<<dim3(PIX/256, BB), 256>>>(x, w_enc, b_enc, pos);

    for (int layer=0; layer<NLAYER; layer++){
        k_fft_fwd<<<dim3(BCK/128, NP/64), 256>>>();
        k_legfwd <<<dim3(BC/128, LL/64, MM), 256>>>(sht_wt);
        k_dhconv <<<dim3(3, CEMB/64, LL), 256>>>(layer);
        k_legbwd <<<dim3(BC/128, KLAT/64, MM), 256>>>(isht_wt);
        k_fft_inv<<<dim3(BCK/128, NLON/64), 256>>>();
        k_mlp1   <<<dim3(PIX/64, HID/128, BB), 256>>>(w1 + (size_t)layer*HID*CEMB,  b1 + layer*HID);
        k_mlp2   <<<dim3(PIX/64, CEMB/128, BB), 256>>>(w2 + (size_t)layer*CEMB*HID, b2 + layer*CEMB);
    }

    k_decoder<<<dim3(PIX/256, BB), 256>>>(w_dec, b_dec, out);
}